// round 13
// baseline (speedup 1.0000x reference)
#include <cuda_runtime.h>

// Chamfer distance via exact grid nearest-neighbor search.
// B=8, Np=Ng=8192, D=3. Points ~ N(0,1) -> uniform grid 64^3 over [-8,8]^3.
// Exact: ring search with conservative geometric lower bounds (+eps slack).
// Distances use the reference's expansion formula p^2+g^2-2p.g.

#define BB 8
#define NN 8192
#define GRID 64
#define NC (GRID * GRID * GRID)      // 262144 cells per segment
#define NSEG 16                       // 2 target-sets x 8 batches
#define NPTS (2 * BB * NN)            // 131072 total (both sets)
#define CS 0.25f
#define LO (-8.0f)
#define INVCS 4.0f
#define EPS 1e-5f
#define NBLK 256                      // prefix blocks per segment (1024 cells each)
#define QBLOCKS (NPTS / 256)          // 512

// seg = t*8 + b; t=0: targets = gt (queries = pred), t=1: targets = pred.
__device__ unsigned g_cnt[NSEG][NC];       // per-cell counts
__device__ unsigned g_off[NSEG][NC];       // local-exclusive prefix; bumped by scatter
__device__ unsigned g_bsum[NSEG][NBLK];    // per-1024-cell-block totals
__device__ unsigned g_bsumx[NSEG][NBLK];   // exclusive scan of g_bsum
__device__ float4   g_pts[NSEG][NN];       // reordered targets (x,y,z,|p|^2)
__device__ double   g_bpart[QBLOCKS];      // per-query-block partial sums

__device__ __forceinline__ int cell_coord(float v) {
    int c = (int)floorf((v - LO) * INVCS);
    return min(GRID - 1, max(0, c));
}
// Distance from q to cell i's interval along one axis (0 if inside).
__device__ __forceinline__ float axis_dist(float q, int i) {
    float lo = LO + i * CS;
    return fmaxf(0.0f, fmaxf(lo - q, q - (lo + CS)));
}

// ---- K0: zero counts ----
__global__ void knn_zero() {
    unsigned idx = blockIdx.x * 1024u + threadIdx.x;   // 4096 x 1024 = NSEG*NC
    ((unsigned*)g_cnt)[idx] = 0u;
}

// ---- K1: count targets per cell ----
__global__ __launch_bounds__(256)
void knn_count(const float* __restrict__ pred, const float* __restrict__ gt) {
    int idx = blockIdx.x * 256 + threadIdx.x;          // 0..NPTS-1
    int t = idx >> 16;
    int b = (idx >> 13) & 7;
    int i = idx & 8191;
    const float* p = (t == 0 ? gt : pred) + ((long)(b * NN + i)) * 3;
    int ix = cell_coord(p[0]), iy = cell_coord(p[1]), iz = cell_coord(p[2]);
    int c = (ix * GRID + iy) * GRID + iz;
    atomicAdd(&g_cnt[t * 8 + b][c], 1u);
}

// ---- K2: per-block local exclusive prefix + block totals ----
__global__ __launch_bounds__(256)
void knn_prefix1() {
    const int seg = blockIdx.y;
    const int blk = blockIdx.x;
    const int tid = threadIdx.x;
    const int base = blk * 1024 + tid * 4;
    unsigned c0 = g_cnt[seg][base + 0];
    unsigned c1 = g_cnt[seg][base + 1];
    unsigned c2 = g_cnt[seg][base + 2];
    unsigned c3 = g_cnt[seg][base + 3];
    unsigned e1 = c0, e2 = c0 + c1, e3 = e2 + c2;
    unsigned tsum = e3 + c3;

    __shared__ unsigned s[256];
    s[tid] = tsum;
    __syncthreads();
    for (int o = 1; o < 256; o <<= 1) {
        unsigned v = (tid >= o) ? s[tid - o] : 0u;
        __syncthreads();
        s[tid] += v;
        __syncthreads();
    }
    unsigned excl = s[tid] - tsum;
    g_off[seg][base + 0] = excl;
    g_off[seg][base + 1] = excl + e1;
    g_off[seg][base + 2] = excl + e2;
    g_off[seg][base + 3] = excl + e3;
    if (tid == 0) g_bsum[seg][blk] = s[255];
}

// ---- K3: exclusive scan of block totals (per segment) ----
__global__ __launch_bounds__(256)
void knn_prefix2() {
    const int seg = blockIdx.x;
    const int tid = threadIdx.x;
    unsigned v = g_bsum[seg][tid];
    __shared__ unsigned s[256];
    s[tid] = v;
    __syncthreads();
    for (int o = 1; o < 256; o <<= 1) {
        unsigned u = (tid >= o) ? s[tid - o] : 0u;
        __syncthreads();
        s[tid] += u;
        __syncthreads();
    }
    g_bsumx[seg][tid] = s[tid] - v;
}

// ---- K4: scatter targets into cell-ordered array ----
__global__ __launch_bounds__(256)
void knn_scatter(const float* __restrict__ pred, const float* __restrict__ gt) {
    int idx = blockIdx.x * 256 + threadIdx.x;
    int t = idx >> 16;
    int b = (idx >> 13) & 7;
    int i = idx & 8191;
    int seg = t * 8 + b;
    const float* p = (t == 0 ? gt : pred) + ((long)(b * NN + i)) * 3;
    float x = p[0], y = p[1], z = p[2];
    int ix = cell_coord(x), iy = cell_coord(y), iz = cell_coord(z);
    int c = (ix * GRID + iy) * GRID + iz;
    unsigned local = atomicAdd(&g_off[seg][c], 1u);     // localExcl + arrivals
    unsigned slot = local + g_bsumx[seg][c >> 10];
    g_pts[seg][slot] = make_float4(x, y, z, x * x + y * y + z * z);
}

// Scan one cell's points; update best.
__device__ __forceinline__ void scan_cell(int xx, int yy, int zz, float ryz,
                                          int seg, float qx, float qy, float qz,
                                          float qw, float& best) {
    if ((unsigned)xx >= (unsigned)GRID) return;
    float ax = axis_dist(qx, xx);
    float bd = ryz + ax * ax;
    if (bd > best + EPS) return;
    int c = (xx * GRID + yy) * GRID + zz;
    unsigned cn = g_cnt[seg][c];
    if (cn == 0u) return;
    unsigned st = g_off[seg][c] - cn + g_bsumx[seg][c >> 10];
    for (unsigned s = st; s < st + cn; s++) {
        float4 p = g_pts[seg][s];
        float d = (qw + p.w) - 2.0f * (qx * p.x + qy * p.y + qz * p.z);
        best = fminf(best, d);
    }
}

// ---- K5: queries (exact ring search) ----
__global__ __launch_bounds__(256)
void knn_query(const float* __restrict__ pred, const float* __restrict__ gt) {
    int idx = blockIdx.x * 256 + threadIdx.x;
    int t = idx >> 16;
    int b = (idx >> 13) & 7;
    int i = idx & 8191;
    int seg = t * 8 + b;
    const float* q = (t == 0 ? pred : gt) + ((long)(b * NN + i)) * 3;
    float qx = q[0], qy = q[1], qz = q[2];
    float qw = qx * qx + qy * qy + qz * qz;
    int ix = cell_coord(qx), iy = cell_coord(qy), iz = cell_coord(qz);

    float best = __int_as_float(0x7F800000);   // +inf

    for (int r = 0; r <= GRID; r++) {
        if (r >= 1) {
            float rb = (r - 1) * CS;            // lower bound for ring r
            if (rb * rb > best + EPS) break;
        }
        for (int dz = -r; dz <= r; dz++) {
            int zz = iz + dz;
            if ((unsigned)zz >= (unsigned)GRID) continue;
            float az = axis_dist(qz, zz);
            float az2 = az * az;
            if (az2 > best + EPS) continue;
            bool zf = (dz == r) || (dz == -r);
            for (int dy = -r; dy <= r; dy++) {
                int yy = iy + dy;
                if ((unsigned)yy >= (unsigned)GRID) continue;
                float ay = axis_dist(qy, yy);
                float ryz = az2 + ay * ay;
                if (ryz > best + EPS) continue;
                bool yf = (dy == r) || (dy == -r);
                if (zf || yf) {
                    for (int dx = -r; dx <= r; dx++)
                        scan_cell(ix + dx, yy, zz, ryz, seg, qx, qy, qz, qw, best);
                } else {
                    scan_cell(ix - r, yy, zz, ryz, seg, qx, qy, qz, qw, best);
                    scan_cell(ix + r, yy, zz, ryz, seg, qx, qy, qz, qw, best);
                }
            }
        }
    }

    // Deterministic partial sums: block tree-reduce, one slot per block.
    __shared__ double sd[256];
    sd[threadIdx.x] = (double)best;
    __syncthreads();
    for (int st = 128; st > 0; st >>= 1) {
        if (threadIdx.x < st) sd[threadIdx.x] += sd[threadIdx.x + st];
        __syncthreads();
    }
    if (threadIdx.x == 0) g_bpart[blockIdx.x] = sd[0];
}

// ---- K6: final fixed-order reduction ----
__global__ __launch_bounds__(512)
void knn_final(float* __restrict__ out) {
    __shared__ double s[512];
    s[threadIdx.x] = g_bpart[threadIdx.x];
    __syncthreads();
    for (int st = 256; st > 0; st >>= 1) {
        if (threadIdx.x < st) s[threadIdx.x] += s[threadIdx.x + st];
        __syncthreads();
    }
    if (threadIdx.x == 0)
        out[0] = (float)(s[0] / (double)(BB * NN));
}

extern "C" void kernel_launch(void* const* d_in, const int* in_sizes, int n_in,
                              void* d_out, int out_size) {
    const float* pred = (const float*)d_in[0];
    const float* gt   = (const float*)d_in[1];
    float* out = (float*)d_out;

    knn_zero<<<(NSEG * NC) / 1024, 1024>>>();
    knn_count<<<NPTS / 256, 256>>>(pred, gt);
    knn_prefix1<<<dim3(NBLK, NSEG), 256>>>();
    knn_prefix2<<<NSEG, 256>>>();
    knn_scatter<<<NPTS / 256, 256>>>(pred, gt);
    knn_query<<<QBLOCKS, 256>>>(pred, gt);
    knn_final<<<1, 512>>>(out);
}

// round 14
// speedup vs baseline: 6.4517x; 6.4517x over previous
#include <cuda_runtime.h>

// Chamfer distance via exact grid nearest-neighbor search, v2.
// B=8, Np=Ng=8192. Grid 32^3 over [-8,8]^3 (cell 0.5).
// - queries run over the cell-sorted point arrays (warp-coherent)
// - per-(x,y)-column z-occupancy bitmasks skip empty cells
// - packed cell descriptors (start<<14 | cnt): one LDG per cell
// - order-independent fixed-point u64 sum: bitwise-deterministic output

#define BB 8
#define NN 8192
#define GRID 32
#define NC (GRID * GRID * GRID)        // 32768 cells per segment
#define NSEG 16                        // 2 target-sets x 8 batches
#define NPTS (2 * BB * NN)             // 131072
#define CS 0.5f
#define LO (-8.0f)
#define INVCS 2.0f
#define EPS 1e-5f
#define NBLK (NC / 1024)               // 32 prefix blocks per segment
#define QBLOCKS (NPTS / 256)           // 512
#define FXS 4398046511104.0            // 2^42 fixed-point scale

__device__ unsigned g_cnt[NSEG][NC];
__device__ unsigned g_off[NSEG][NC];        // local excl prefix; scatter cursor
__device__ unsigned g_bsum[NSEG][NBLK];
__device__ unsigned g_bsumx[NSEG][NBLK];
__device__ unsigned g_cell[NSEG][NC];       // start<<14 | cnt
__device__ unsigned g_mask[NSEG][GRID * GRID];  // z-occupancy per (x,y) column
__device__ float4   g_pts[NSEG][NN];        // cell-sorted (x,y,z,|p|^2)
__device__ unsigned long long g_isum;

__device__ __forceinline__ int cell_coord(float v) {
    int c = (int)floorf((v - LO) * INVCS);
    return min(GRID - 1, max(0, c));
}
__device__ __forceinline__ float axis_dist(float q, int i) {
    float lo = LO + i * CS;
    return fmaxf(0.0f, fmaxf(lo - q, q - (lo + CS)));
}

// ---- K0: zero counts, masks, sum ----
__global__ void knn_zero() {
    unsigned idx = blockIdx.x * 1024u + threadIdx.x;
    if (idx < NSEG * NC) ((unsigned*)g_cnt)[idx] = 0u;
    else if (idx < NSEG * NC + NSEG * GRID * GRID)
        ((unsigned*)g_mask)[idx - NSEG * NC] = 0u;
    else if (idx == NSEG * NC + NSEG * GRID * GRID) g_isum = 0ull;
}

// ---- K1: count + column masks ----
__global__ __launch_bounds__(256)
void knn_count(const float* __restrict__ pred, const float* __restrict__ gt) {
    int idx = blockIdx.x * 256 + threadIdx.x;
    int t = idx >> 16, b = (idx >> 13) & 7, i = idx & 8191;
    const float* p = (t == 0 ? gt : pred) + ((long)(b * NN + i)) * 3;
    int ix = cell_coord(p[0]), iy = cell_coord(p[1]), iz = cell_coord(p[2]);
    int seg = t * 8 + b;
    atomicAdd(&g_cnt[seg][((ix << 5) | iy) << 5 | iz], 1u);
    atomicOr(&g_mask[seg][(ix << 5) | iy], 1u << iz);
}

// ---- K2: per-1024-cell-block exclusive prefix + block totals ----
__global__ __launch_bounds__(256)
void knn_prefix1() {
    const int seg = blockIdx.y, blk = blockIdx.x, tid = threadIdx.x;
    const int base = blk * 1024 + tid * 4;
    unsigned c0 = g_cnt[seg][base], c1 = g_cnt[seg][base + 1];
    unsigned c2 = g_cnt[seg][base + 2], c3 = g_cnt[seg][base + 3];
    unsigned e1 = c0, e2 = c0 + c1, e3 = e2 + c2;
    unsigned tsum = e3 + c3;
    __shared__ unsigned s[256];
    s[tid] = tsum;
    __syncthreads();
    for (int o = 1; o < 256; o <<= 1) {
        unsigned v = (tid >= o) ? s[tid - o] : 0u;
        __syncthreads();
        s[tid] += v;
        __syncthreads();
    }
    unsigned excl = s[tid] - tsum;
    g_off[seg][base]     = excl;
    g_off[seg][base + 1] = excl + e1;
    g_off[seg][base + 2] = excl + e2;
    g_off[seg][base + 3] = excl + e3;
    if (tid == 0) g_bsum[seg][blk] = s[255];
}

// ---- K3: scan 32 block totals per segment ----
__global__ void knn_prefix2() {
    const int seg = blockIdx.x, tid = threadIdx.x;   // 32 threads
    unsigned v = g_bsum[seg][tid];
    __shared__ unsigned s[32];
    s[tid] = v;
    __syncwarp();
    for (int o = 1; o < 32; o <<= 1) {
        unsigned u = (tid >= o) ? s[tid - o] : 0u;
        __syncwarp();
        s[tid] += u;
        __syncwarp();
    }
    g_bsumx[seg][tid] = s[tid] - v;
}

// ---- K4: pack per-cell (start, count) into one word ----
__global__ __launch_bounds__(1024)
void knn_cellpack() {
    unsigned idx = blockIdx.x * 1024u + threadIdx.x;   // NSEG*NC
    int seg = idx >> 15, c = idx & (NC - 1);
    unsigned start = g_off[seg][c] + g_bsumx[seg][c >> 10];
    g_cell[seg][c] = (start << 14) | g_cnt[seg][c];
}

// ---- K5: scatter points into cell order ----
__global__ __launch_bounds__(256)
void knn_scatter(const float* __restrict__ pred, const float* __restrict__ gt) {
    int idx = blockIdx.x * 256 + threadIdx.x;
    int t = idx >> 16, b = (idx >> 13) & 7, i = idx & 8191;
    int seg = t * 8 + b;
    const float* p = (t == 0 ? gt : pred) + ((long)(b * NN + i)) * 3;
    float x = p[0], y = p[1], z = p[2];
    int ix = cell_coord(x), iy = cell_coord(y), iz = cell_coord(z);
    int c = ((ix << 5) | iy) << 5 | iz;
    unsigned local = atomicAdd(&g_off[seg][c], 1u);
    g_pts[seg][local + g_bsumx[seg][c >> 10]] =
        make_float4(x, y, z, x * x + y * y + z * z);
}

__device__ __forceinline__ void scan_cell(int tseg, int c, float qx, float qy,
                                          float qz, float qw, float& best) {
    unsigned pc = g_cell[tseg][c];
    unsigned cn = pc & 16383u;
    unsigned st = pc >> 14;
    for (unsigned s = st; s < st + cn; s++) {
        float4 p = g_pts[tseg][s];
        float d = (qw + p.w) - 2.0f * (qx * p.x + qy * p.y + qz * p.z);
        best = fminf(best, d);
    }
}

// ---- K6: exact ring search over cell-sorted queries ----
__global__ __launch_bounds__(256)
void knn_query() {
    int idx = blockIdx.x * 256 + threadIdx.x;
    int qseg = idx >> 13, i = idx & 8191;
    int tseg = qseg ^ 8;
    float4 q = g_pts[qseg][i];
    float qx = q.x, qy = q.y, qz = q.z, qw = q.w;
    int ix = cell_coord(qx), iy = cell_coord(qy), iz = cell_coord(qz);

    float best = __int_as_float(0x7F800000);

    for (int r = 0; r < GRID; r++) {
        if (r >= 1) {
            float rb = (r - 1) * CS;
            if (rb * rb > best + EPS) break;
        }
        for (int dx = -r; dx <= r; dx++) {
            int xx = ix + dx;
            if ((unsigned)xx >= (unsigned)GRID) continue;
            float ax = axis_dist(qx, xx);
            float ax2 = ax * ax;
            if (ax2 > best + EPS) continue;
            bool xf = (dx == r) || (dx == -r);
            for (int dy = -r; dy <= r; dy++) {
                int yy = iy + dy;
                if ((unsigned)yy >= (unsigned)GRID) continue;
                float ay = axis_dist(qy, yy);
                float rxy = ax2 + ay * ay;
                if (rxy > best + EPS) continue;
                unsigned mask = g_mask[tseg][(xx << 5) | yy];
                if (!mask) continue;
                int cbase = (((xx << 5) | yy) << 5);
                if (xf || dy == r || dy == -r) {
                    // face column: all |dz|<=r cells are ring-r cells
                    int zlo = max(0, iz - r), zhi = min(GRID - 1, iz + r);
                    unsigned m = mask & (0xFFFFFFFFu << zlo)
                                      & (0xFFFFFFFFu >> (31 - zhi));
                    while (m) {
                        int zz = __ffs(m) - 1;
                        m &= m - 1;
                        float az = axis_dist(qz, zz);
                        if (rxy + az * az > best + EPS) continue;
                        scan_cell(tseg, cbase | zz, qx, qy, qz, qw, best);
                    }
                } else {
                    // interior column: only dz = +-r
                    int zz = iz - r;
                    if (zz >= 0 && ((mask >> zz) & 1u)) {
                        float az = axis_dist(qz, zz);
                        if (rxy + az * az <= best + EPS)
                            scan_cell(tseg, cbase | zz, qx, qy, qz, qw, best);
                    }
                    zz = iz + r;
                    if (zz < GRID && ((mask >> zz) & 1u)) {
                        float az = axis_dist(qz, zz);
                        if (rxy + az * az <= best + EPS)
                            scan_cell(tseg, cbase | zz, qx, qy, qz, qw, best);
                    }
                }
            }
        }
    }

    // Order-independent fixed-point sum (deterministic vs scatter order).
    unsigned long long fx = (unsigned long long)((double)best * FXS + 0.5);
    __shared__ unsigned long long ss[256];
    ss[threadIdx.x] = fx;
    __syncthreads();
    for (int st = 128; st > 0; st >>= 1) {
        if (threadIdx.x < st) ss[threadIdx.x] += ss[threadIdx.x + st];
        __syncthreads();
    }
    if (threadIdx.x == 0) atomicAdd(&g_isum, ss[0]);
}

// ---- K7: finalize ----
__global__ void knn_final(float* __restrict__ out) {
    out[0] = (float)((double)g_isum / FXS / (double)(BB * NN));
}

extern "C" void kernel_launch(void* const* d_in, const int* in_sizes, int n_in,
                              void* d_out, int out_size) {
    const float* pred = (const float*)d_in[0];
    const float* gt   = (const float*)d_in[1];
    float* out = (float*)d_out;

    int zero_elems = NSEG * NC + NSEG * GRID * GRID + 1;
    knn_zero<<<(zero_elems + 1023) / 1024, 1024>>>();
    knn_count<<<NPTS / 256, 256>>>(pred, gt);
    knn_prefix1<<<dim3(NBLK, NSEG), 256>>>();
    knn_prefix2<<<NSEG, 32>>>();
    knn_cellpack<<<(NSEG * NC) / 1024, 1024>>>();
    knn_scatter<<<NPTS / 256, 256>>>(pred, gt);
    knn_query<<<QBLOCKS, 256>>>();
    knn_final<<<1, 1>>>(out);
}